// round 8
// baseline (speedup 1.0000x reference)
#include <cuda_runtime.h>
#include <cuda_fp16.h>

// WarpingLayer v7: stage-fused same-stream pipeline.
//   Stage k (one kernel launch): even blocks transpose batch k (NCHW f32 ->
//   NHWC f16), odd blocks gather batch k-1 (bilinear from L2-hot xt slice).
//   9 sequential launches on ONE stream give exactly the required dependency
//   (gather(k-1) <= end of launch k-1 which contained transpose(k-1)) with
//   full intra-launch overlap of DRAM-bound and L1-bound work. No events.
// Mask arithmetic reproduces the JAX reference fp32 op ordering exactly.

namespace {

constexpr int B = 8;
constexpr int C = 128;
constexpr int H = 128;
constexpr int W = 256;
constexpr int HW = H * W;                     // 32768

// 67 MB fp16 scratch for the transposed image (__device__ global: allowed).
__device__ __half g_xt[(size_t)B * HW * C];

// ---------------- transpose role: one 32c x 128hw tile of batch tb ----------------
__device__ __forceinline__ void do_transpose(const float* __restrict__ x,
                                             int tb, int vbid, float* smem)
{
    float (*tile)[133] = (float(*)[133])smem;
    const int hw0 = (vbid & 255) * 128;        // HW/128 = 256 tiles
    const int c0  = (vbid >> 8) * 32;          // C/32 = 4
    const int tx  = threadIdx.x & 31;
    const int ty  = threadIdx.x >> 5;          // 0..7

    const float* px = x + (size_t)tb * C * HW;
    #pragma unroll
    for (int i = 0; i < 4; ++i) {
        const int cl = ty + i * 8;             // 0..31
        const float4 v = __ldcs((const float4*)(px + (size_t)(c0 + cl) * HW + hw0) + tx);
        float* t = &tile[cl][4 * tx];
        t[0] = v.x; t[1] = v.y; t[2] = v.z; t[3] = v.w;
    }
    __syncthreads();

    __half* pt = g_xt + (size_t)tb * HW * C;
    const int cpair = tx & 15;                 // channel pair 0..15
    const int hwsub = tx >> 4;                 // 0..1
    #pragma unroll
    for (int i = 0; i < 8; ++i) {
        const int hwl = (i * 8 + ty) * 2 + hwsub;          // 0..127
        const __half2 hv = __floats2half2_rn(tile[cpair * 2][hwl],
                                             tile[cpair * 2 + 1][hwl]);
        *(__half2*)(pt + (size_t)(hw0 + hwl) * C + c0 + cpair * 2) = hv;
    }
}

// ---------------- gather role: 32 pixels (same gb,h) ----------------
// Warp computes 4 pixels; params in lanes 0..3, shfl-broadcast. Lane l gathers
// channels 4l..4l+3 (one 8B uint2 load per corner: 256B/warp, coalesced).
__device__ __forceinline__ void do_gather(const float* __restrict__ flow,
                                          float* __restrict__ out,
                                          int gb, int vbid, float* smem)
{
    float (*tile)[129] = (float(*)[129])smem;

    const int tid  = threadIdx.x;
    const int warp = tid >> 5;
    const int lane = tid & 31;

    const int pix = vbid * 32;                 // within batch gb
    const int h  = (pix >> 8) & (H - 1);
    const int w0 = pix & (W - 1);

    const __half* xt = g_xt + (size_t)gb * HW * C;

    float m00 = 0.f, m01 = 0.f, m10 = 0.f, m11 = 0.f, ones_val = 0.f;
    int o00 = 0, o01 = 0, o10 = 0, o11 = 0;
    if (lane < 4) {
        const int w = w0 + warp * 4 + lane;
        const int fbase = gb * 2 * HW + h * W + w;
        const float fx = __ldg(flow + fbase);
        const float fy = __ldg(flow + fbase + HW);

        // Reference-exact fp32 ordering:
        const float flo_w = __fmul_rn(__fdiv_rn(__fmul_rn(fx, 2.0f), (float)(W - 1)), 1.0f);
        const float flo_h = __fmul_rn(__fdiv_rn(__fmul_rn(fy, 2.0f), (float)(H - 1)), 1.0f);
        const float step_x = __fdiv_rn(2.0f, (float)(W - 1));
        const float step_y = __fdiv_rn(2.0f, (float)(H - 1));
        const float gx = __fadd_rn(-1.0f, __fmul_rn((float)w, step_x));
        const float gy = __fadd_rn(-1.0f, __fmul_rn((float)h, step_y));

        const float ix = __fmul_rn(__fmul_rn(__fadd_rn(__fadd_rn(gx, flo_w), 1.0f), 0.5f), (float)(W - 1));
        const float iy = __fmul_rn(__fmul_rn(__fadd_rn(__fadd_rn(gy, flo_h), 1.0f), 0.5f), (float)(H - 1));

        const float x0f = floorf(ix);
        const float y0f = floorf(iy);
        const float x1f = __fadd_rn(x0f, 1.0f);
        const float y1f = __fadd_rn(y0f, 1.0f);

        const float wx1 = __fadd_rn(ix, -x0f);
        const float wx0 = __fadd_rn(1.0f, -wx1);
        const float wy1 = __fadd_rn(iy, -y0f);
        const float wy0 = __fadd_rn(1.0f, -wy1);

        const bool vx0 = (x0f >= 0.0f) && (x0f <= (float)(W - 1));
        const bool vx1 = (x1f >= 0.0f) && (x1f <= (float)(W - 1));
        const bool vy0 = (y0f >= 0.0f) && (y0f <= (float)(H - 1));
        const bool vy1 = (y1f >= 0.0f) && (y1f <= (float)(H - 1));

        m00 = (vx0 && vy0) ? __fmul_rn(wx0, wy0) : 0.0f;
        m01 = (vx1 && vy0) ? __fmul_rn(wx1, wy0) : 0.0f;
        m10 = (vx0 && vy1) ? __fmul_rn(wx0, wy1) : 0.0f;
        m11 = (vx1 && vy1) ? __fmul_rn(wx1, wy1) : 0.0f;
        ones_val = __fadd_rn(__fadd_rn(__fadd_rn(m00, m01), m10), m11);

        const int xi0 = min(max((int)x0f, 0), W - 1);
        const int xi1 = min(max((int)x1f, 0), W - 1);
        const int yi0 = min(max((int)y0f, 0), H - 1);
        const int yi1 = min(max((int)y1f, 0), H - 1);
        o00 = yi0 * W + xi0;
        o01 = yi0 * W + xi1;
        o10 = yi1 * W + xi0;
        o11 = yi1 * W + xi1;
    }

    const int cc = lane * 4;

    #pragma unroll
    for (int pp = 0; pp < 4; ++pp) {
        const float ov = __shfl_sync(0xffffffffu, ones_val, pp);
        const int p = warp * 4 + pp;
        float v0, v1, v2, v3;
        if (ov < 0.99999f) {
            v0 = v1 = v2 = v3 = 0.0f;
        } else {
            const float w00 = __shfl_sync(0xffffffffu, m00, pp);
            const float w01 = __shfl_sync(0xffffffffu, m01, pp);
            const float w10 = __shfl_sync(0xffffffffu, m10, pp);
            const float w11 = __shfl_sync(0xffffffffu, m11, pp);
            const int   a00 = __shfl_sync(0xffffffffu, o00, pp);
            const int   a01 = __shfl_sync(0xffffffffu, o01, pp);
            const int   a10 = __shfl_sync(0xffffffffu, o10, pp);
            const int   a11 = __shfl_sync(0xffffffffu, o11, pp);

            // 4 halfs (8B) per corner per lane — one uint2 LDG per corner.
            const uint2 r00 = *(const uint2*)(xt + (size_t)a00 * C + cc);
            const uint2 r01 = *(const uint2*)(xt + (size_t)a01 * C + cc);
            const uint2 r10 = *(const uint2*)(xt + (size_t)a10 * C + cc);
            const uint2 r11 = *(const uint2*)(xt + (size_t)a11 * C + cc);

            const float2 f00a = __half22float2(*(const __half2*)&r00.x);
            const float2 f00b = __half22float2(*(const __half2*)&r00.y);
            const float2 f01a = __half22float2(*(const __half2*)&r01.x);
            const float2 f01b = __half22float2(*(const __half2*)&r01.y);
            const float2 f10a = __half22float2(*(const __half2*)&r10.x);
            const float2 f10b = __half22float2(*(const __half2*)&r10.y);
            const float2 f11a = __half22float2(*(const __half2*)&r11.x);
            const float2 f11b = __half22float2(*(const __half2*)&r11.y);

            v0 = fmaf(f11a.x, w11, fmaf(f10a.x, w10, fmaf(f01a.x, w01, f00a.x * w00)));
            v1 = fmaf(f11a.y, w11, fmaf(f10a.y, w10, fmaf(f01a.y, w01, f00a.y * w00)));
            v2 = fmaf(f11b.x, w11, fmaf(f10b.x, w10, fmaf(f01b.x, w01, f00b.x * w00)));
            v3 = fmaf(f11b.y, w11, fmaf(f10b.y, w10, fmaf(f01b.y, w01, f00b.y * w00)));
        }
        float* srow = &tile[p][cc];
        srow[0] = v0; srow[1] = v1; srow[2] = v2; srow[3] = v3;
    }

    __syncthreads();

    // NCHW write-back: warp = fixed channel, lanes = consecutive w (coalesced).
    const int p  = tid & 31;
    const int c0 = tid >> 5;
    float* po = out + (size_t)gb * C * HW + (size_t)h * W + w0 + p;
    #pragma unroll
    for (int i = 0; i < 16; ++i) {
        const int c = c0 + i * 8;
        __stcs(po + (size_t)c * HW, tile[p][c]);
    }
}

// ---------------- fused stage kernel ----------------
__global__ __launch_bounds__(256) void stage_kernel(
    const float* __restrict__ x,
    const float* __restrict__ flow,
    float* __restrict__ out,
    int tb, int gb)
{
    __shared__ float smem[32 * 133];
    const int role = blockIdx.x & 1;           // interleave roles across SMs
    const int vbid = blockIdx.x >> 1;          // 0..1023 per role
    if (role == 0) {
        if (tb < 0) return;
        do_transpose(x, tb, vbid, smem);
    } else {
        if (gb < 0) return;
        do_gather(flow, out, gb, vbid, smem);
    }
}

}  // namespace

extern "C" void kernel_launch(void* const* d_in, const int* in_sizes, int n_in,
                              void* d_out, int out_size) {
    const float* x    = (const float*)d_in[0];
    const float* flow = (const float*)d_in[1];
    float* out        = (float*)d_out;

    // 9 stages on one stream: stage k = transpose(k) [k<8] + gather(k-1) [k>0].
    // Stream ordering alone provides the dependency; roles overlap in-launch.
    for (int k = 0; k <= B; ++k) {
        const int tb = (k < B) ? k : -1;
        const int gb = k - 1;                  // -1 at k=0 (skipped by blocks)
        stage_kernel<<<2048, 256>>>(x, flow, out, tb, gb);
    }
}

// round 9
// speedup vs baseline: 1.4905x; 1.4905x over previous
#include <cuda_runtime.h>
#include <cuda_fp16.h>

// WarpingLayer v9: serial two-pass, gather de-serialized via precomputed params.
//   Pass 1 (one launch): transpose x NCHW f32 -> xt NHWC f16  (blockIdx.y<4)
//                        + param prep from flow (blockIdx.y==4): per pixel
//                        4 bilinear weights (validity folded) + 4 clamped offsets.
//   Pass 2: branchless gather: broadcast param loads (no shfl, no coord math),
//           16 independent corner LDGs per warp, fp16 conflict-free smem staging,
//           coalesced NCHW f32 writeback (__stcs).
// Param math reproduces the JAX reference fp32 op ordering exactly.

namespace {

constexpr int B = 8;
constexpr int C = 128;
constexpr int H = 128;
constexpr int W = 256;
constexpr int HW = H * W;                     // 32768

// Scratch (__device__ globals: allowed).
__device__ __half g_xt[(size_t)B * HW * C];   // 67 MB transposed image
__device__ float4 g_wpar[(size_t)B * HW];     // 16.8 MB weights (4/pixel)
__device__ int4   g_opar[(size_t)B * HW];     // 16.8 MB offsets (4/pixel)

// ---------------- param prep: one pixel per thread ----------------
__device__ __forceinline__ void do_params(const float* __restrict__ flow,
                                          int b, int pix)
{
    const int w = pix & (W - 1);
    const int h = pix >> 8;

    const int fbase = b * 2 * HW + h * W + w;
    const float fx = __ldg(flow + fbase);
    const float fy = __ldg(flow + fbase + HW);

    // Reference-exact fp32 ordering:
    const float flo_w = __fmul_rn(__fdiv_rn(__fmul_rn(fx, 2.0f), (float)(W - 1)), 1.0f);
    const float flo_h = __fmul_rn(__fdiv_rn(__fmul_rn(fy, 2.0f), (float)(H - 1)), 1.0f);
    const float step_x = __fdiv_rn(2.0f, (float)(W - 1));
    const float step_y = __fdiv_rn(2.0f, (float)(H - 1));
    const float gx = __fadd_rn(-1.0f, __fmul_rn((float)w, step_x));
    const float gy = __fadd_rn(-1.0f, __fmul_rn((float)h, step_y));

    const float ix = __fmul_rn(__fmul_rn(__fadd_rn(__fadd_rn(gx, flo_w), 1.0f), 0.5f), (float)(W - 1));
    const float iy = __fmul_rn(__fmul_rn(__fadd_rn(__fadd_rn(gy, flo_h), 1.0f), 0.5f), (float)(H - 1));

    const float x0f = floorf(ix);
    const float y0f = floorf(iy);
    const float x1f = __fadd_rn(x0f, 1.0f);
    const float y1f = __fadd_rn(y0f, 1.0f);

    const float wx1 = __fadd_rn(ix, -x0f);
    const float wx0 = __fadd_rn(1.0f, -wx1);
    const float wy1 = __fadd_rn(iy, -y0f);
    const float wy0 = __fadd_rn(1.0f, -wy1);

    const bool vx0 = (x0f >= 0.0f) && (x0f <= (float)(W - 1));
    const bool vx1 = (x1f >= 0.0f) && (x1f <= (float)(W - 1));
    const bool vy0 = (y0f >= 0.0f) && (y0f <= (float)(H - 1));
    const bool vy1 = (y1f >= 0.0f) && (y1f <= (float)(H - 1));

    float m00 = (vx0 && vy0) ? __fmul_rn(wx0, wy0) : 0.0f;
    float m01 = (vx1 && vy0) ? __fmul_rn(wx1, wy0) : 0.0f;
    float m10 = (vx0 && vy1) ? __fmul_rn(wx0, wy1) : 0.0f;
    float m11 = (vx1 && vy1) ? __fmul_rn(wx1, wy1) : 0.0f;

    // ones_val in ref order; fold binary mask into the weights themselves.
    const float ones_val = __fadd_rn(__fadd_rn(__fadd_rn(m00, m01), m10), m11);
    if (ones_val < 0.99999f) { m00 = m01 = m10 = m11 = 0.0f; }

    const int xi0 = min(max((int)x0f, 0), W - 1);
    const int xi1 = min(max((int)x1f, 0), W - 1);
    const int yi0 = min(max((int)y0f, 0), H - 1);
    const int yi1 = min(max((int)y1f, 0), H - 1);

    const int gp = b * HW + pix;
    g_wpar[gp] = make_float4(m00, m01, m10, m11);
    g_opar[gp] = make_int4(yi0 * W + xi0, yi0 * W + xi1,
                           yi1 * W + xi0, yi1 * W + xi1);
}

// ---------------- Pass 1: transpose + param prep ----------------
__global__ __launch_bounds__(256) void transpose_prep_kernel(
    const float* __restrict__ x,
    const float* __restrict__ flow)
{
    const int b = blockIdx.z;

    if (blockIdx.y == 4) {                     // param-prep role
        if (blockIdx.x >= 128) return;         // 128 blocks x 256 thr = 32768 px
        do_params(flow, b, blockIdx.x * 256 + threadIdx.x);
        return;
    }

    __shared__ float tile[32][133];
    const int hw0 = blockIdx.x * 128;
    const int c0  = blockIdx.y * 32;
    const int tx  = threadIdx.x & 31;
    const int ty  = threadIdx.x >> 5;          // 0..7

    const float* px = x + (size_t)b * C * HW;
    #pragma unroll
    for (int i = 0; i < 4; ++i) {
        const int cl = ty + i * 8;             // 0..31
        const float4 v = __ldcs((const float4*)(px + (size_t)(c0 + cl) * HW + hw0) + tx);
        float* t = &tile[cl][4 * tx];
        t[0] = v.x; t[1] = v.y; t[2] = v.z; t[3] = v.w;
    }
    __syncthreads();

    __half* pt = g_xt + (size_t)b * HW * C;
    const int cpair = tx & 15;                 // channel pair 0..15
    const int hwsub = tx >> 4;                 // 0..1
    #pragma unroll
    for (int i = 0; i < 8; ++i) {
        const int hwl = (i * 8 + ty) * 2 + hwsub;          // 0..127
        const __half2 hv = __floats2half2_rn(tile[cpair * 2][hwl],
                                             tile[cpair * 2 + 1][hwl]);
        *(__half2*)(pt + (size_t)(hw0 + hwl) * C + c0 + cpair * 2) = hv;
    }
}

// ---------------- Pass 2: branchless gather ----------------
// Block = 8 warps = 32 pixels (same b,h). Warp computes 4 pixels; params come
// from broadcast LDG.128s (same address across lanes). Lane l gathers channels
// 4l..4l+3: one 8B uint2 load per corner (256B/warp, coalesced). Staging tile
// fp16 rows of 130 halfs: stores contiguous per row; readback bank (p+c/2)%32.
__global__ __launch_bounds__(256) void warp_gather_kernel(float* __restrict__ out)
{
    __shared__ __half tile[32][130];           // 8320 B

    const int tid  = threadIdx.x;
    const int warp = tid >> 5;
    const int lane = tid & 31;

    const int pix = ((int)gridDim.x - 1 - (int)blockIdx.x) * 32;  // reversed
    const int b  = pix >> 15;
    const int h  = (pix >> 8) & (H - 1);
    const int w0 = pix & (W - 1);

    const __half* xt = g_xt + (size_t)b * HW * C;
    const int cc = lane * 4;

    #pragma unroll
    for (int pp = 0; pp < 4; ++pp) {
        const int p  = warp * 4 + pp;
        const int gp = pix + p;                // global pixel (b folded in pix)

        const float4 wv = __ldg(&g_wpar[gp]);  // broadcast (uniform address)
        const int4   ov = __ldg(&g_opar[gp]);

        // 4 independent 8B corner loads (weights already carry mask zeros).
        const uint2 r00 = *(const uint2*)(xt + (size_t)ov.x * C + cc);
        const uint2 r01 = *(const uint2*)(xt + (size_t)ov.y * C + cc);
        const uint2 r10 = *(const uint2*)(xt + (size_t)ov.z * C + cc);
        const uint2 r11 = *(const uint2*)(xt + (size_t)ov.w * C + cc);

        const float2 f00a = __half22float2(*(const __half2*)&r00.x);
        const float2 f00b = __half22float2(*(const __half2*)&r00.y);
        const float2 f01a = __half22float2(*(const __half2*)&r01.x);
        const float2 f01b = __half22float2(*(const __half2*)&r01.y);
        const float2 f10a = __half22float2(*(const __half2*)&r10.x);
        const float2 f10b = __half22float2(*(const __half2*)&r10.y);
        const float2 f11a = __half22float2(*(const __half2*)&r11.x);
        const float2 f11b = __half22float2(*(const __half2*)&r11.y);

        const float v0 = fmaf(f11a.x, wv.w, fmaf(f10a.x, wv.z, fmaf(f01a.x, wv.y, f00a.x * wv.x)));
        const float v1 = fmaf(f11a.y, wv.w, fmaf(f10a.y, wv.z, fmaf(f01a.y, wv.y, f00a.y * wv.x)));
        const float v2 = fmaf(f11b.x, wv.w, fmaf(f10b.x, wv.z, fmaf(f01b.x, wv.y, f00b.x * wv.x)));
        const float v3 = fmaf(f11b.y, wv.w, fmaf(f10b.y, wv.z, fmaf(f01b.y, wv.y, f00b.y * wv.x)));

        // Two half2 stores, contiguous within row p -> conflict-free.
        __half2* dst = (__half2*)&tile[p][cc];
        dst[0] = __floats2half2_rn(v0, v1);
        dst[1] = __floats2half2_rn(v2, v3);
    }

    __syncthreads();

    // NCHW write-back: warp = fixed channel, lanes = consecutive w (coalesced).
    const int p  = tid & 31;
    const int c0 = tid >> 5;
    float* po = out + (size_t)b * C * HW + (size_t)h * W + w0 + p;
    #pragma unroll
    for (int i = 0; i < 16; ++i) {
        const int c = c0 + i * 8;
        __stcs(po + (size_t)c * HW, __half2float(tile[p][c]));
    }
}

}  // namespace

extern "C" void kernel_launch(void* const* d_in, const int* in_sizes, int n_in,
                              void* d_out, int out_size) {
    const float* x    = (const float*)d_in[0];
    const float* flow = (const float*)d_in[1];
    float* out        = (float*)d_out;

    dim3 tgrid(HW / 128, 5, B);                // y<4: transpose tiles, y==4: prep
    transpose_prep_kernel<<<tgrid, 256>>>(x, flow);

    const int nblocks = (B * HW) / 32;         // 8192
    warp_gather_kernel<<<nblocks, 256>>>(out);
}